// round 6
// baseline (speedup 1.0000x reference)
#include <cuda_runtime.h>
#include <cuda_bf16.h>
#include <cstdint>
#include <math.h>

// Problem constants
#define LSEQ   4096
#define DEMB   256
#define HID    256          // per-direction hidden
#define G4H    1024         // 4*HID
#define NT     24
#define START_TAG 22
#define STOP_TAG  23
#define NEGINF (-1.0e6f)

// ---------------- scratch (device globals; no allocation allowed) ----------------
__device__ float g_xp[2][LSEQ * G4H];      // input projections per direction (scan order)
__device__ float g_lstm_out[LSEQ * 512];   // [t][0:256)=fwd h, [256:512)=bwd h (final order)
__device__ float g_feats[LSEQ * NT];

// ---------------- helpers ----------------
__device__ __forceinline__ uint32_t s2u(const void* p) {
    return (uint32_t)__cvta_generic_to_shared(p);
}
__device__ __forceinline__ void dsmem_st_f32(uint32_t laddr, int peer, float v) {
    asm volatile(
        "{\n\t.reg .b32 r;\n\t"
        "mapa.shared::cluster.u32 r, %0, %1;\n\t"
        "st.shared::cluster.f32 [r], %2;\n\t}"
        :: "r"(laddr), "r"(peer), "f"(v) : "memory");
}
__device__ __forceinline__ void cluster_sync_() {
    asm volatile("barrier.cluster.arrive.aligned;" ::: "memory");
    asm volatile("barrier.cluster.wait.aligned;" ::: "memory");
}
__device__ __forceinline__ float sigmoidf_(float x) {
    return 1.0f / (1.0f + expf(-x));
}

// ---------------- kernel 1: embedding gather + input projection ----------------
// xp[dir][s][row] = dot(emb[tok(s)], W_ih[row]) + b_ih[row] + b_hh[row]
// dir==0: tok(s) = sentence[s];  dir==1: tok(s) = sentence[L-1-s]  (reversed scan input)
// Block: 1024 threads (one per gate-row), covers 8 timesteps; W row loaded once, used 8x.
__global__ __launch_bounds__(1024, 1)
void proj_kernel(const int* __restrict__ sent, const float* __restrict__ emb,
                 const float* __restrict__ Wf, const float* __restrict__ bihf,
                 const float* __restrict__ bhhf,
                 const float* __restrict__ Wb, const float* __restrict__ bihb,
                 const float* __restrict__ bhhb)
{
    __shared__ float4 xs[8][64];     // 8 timesteps x 256 floats
    const int dir = blockIdx.y;
    const int t0  = blockIdx.x * 8;
    const int tid = threadIdx.x;

    if (tid < 512) {
        int tt = tid >> 6, k4 = tid & 63;
        int s  = t0 + tt;
        int tok = sent[dir ? (LSEQ - 1 - s) : s];
        xs[tt][k4] = ((const float4*)emb)[(size_t)tok * 64 + k4];
    }
    __syncthreads();

    const float* W = dir ? Wb : Wf;
    const int row = tid;
    const float bias = dir ? (bihb[row] + bhhb[row]) : (bihf[row] + bhhf[row]);
    float acc[8];
#pragma unroll
    for (int i = 0; i < 8; i++) acc[i] = bias;

    const float4* W4 = (const float4*)(W + (size_t)row * DEMB);
#pragma unroll 8
    for (int k4 = 0; k4 < 64; k4++) {
        float4 w4 = __ldg(&W4[k4]);
#pragma unroll
        for (int tt = 0; tt < 8; tt++) {
            float4 x4 = xs[tt][k4];
            acc[tt] += w4.x * x4.x + w4.y * x4.y + w4.z * x4.z + w4.w * x4.w;
        }
    }
    float* out = g_xp[dir];
#pragma unroll
    for (int tt = 0; tt < 8; tt++)
        out[(size_t)(t0 + tt) * G4H + row] = acc[tt];
}

// ---------------- kernel 2: the sequential LSTM recurrence ----------------
// Grid: 16 CTAs, cluster of 8. Cluster 0 = forward, cluster 1 = backward.
// Each CTA owns h-slice [rank*32, rank*32+32): the 128 gate rows {g*256 + rank*32 + j}.
// 512 threads: tid = kq*128 + lr; lr = g*32 + j (local gate row), kq selects K range [kq*64, kq*64+64).
// W_hh slice lives in registers (64 floats/thread). h (256) lives in double-buffered SMEM,
// broadcast cluster-wide via DSMEM stores; one cluster.sync per step.
__global__ __launch_bounds__(512, 1) __cluster_dims__(8, 1, 1)
void lstm_kernel(const float* __restrict__ h0, const float* __restrict__ c0,
                 const float* __restrict__ Whh_f, const float* __restrict__ Whh_b)
{
    __shared__ float hb[2][HID];
    __shared__ float part[4][128];

    const int tid = threadIdx.x;
    int rank;
    asm("mov.u32 %0, %%cluster_ctarank;" : "=r"(rank));
    const int dir = blockIdx.x >> 3;

    const float* Whh = dir ? Whh_b : Whh_f;
    const float* xp  = g_xp[dir];

    const int lr = tid & 127;
    const int kq = tid >> 7;
    const int g  = lr >> 5;
    const int j  = lr & 31;
    const int grow = g * 256 + rank * 32 + j;   // global gate row
    const int k0   = kq * 64;

    float w[64];
#pragma unroll
    for (int kk = 0; kk < 64; kk++)
        w[kk] = __ldg(&Whh[(size_t)grow * HID + k0 + kk]);

    // init h buffer (everyone loads full h0 for this direction)
    if (tid < HID) hb[0][tid] = h0[dir * HID + tid];

    float c = 0.0f;
    float xpv[4] = {0.f, 0.f, 0.f, 0.f};
    if (tid < 32) {
        c = c0[dir * HID + rank * 32 + tid];
#pragma unroll
        for (int gg = 0; gg < 4; gg++)
            xpv[gg] = xp[(size_t)0 * G4H + gg * 256 + rank * 32 + tid];
    }
    __syncthreads();
    cluster_sync_();

    int p = 0;
    for (int t = 0; t < LSEQ; t++) {
        // prefetch next step's xp rows (hidden behind this step's dot compute)
        float xpn[4] = {0.f, 0.f, 0.f, 0.f};
        if (tid < 32 && t + 1 < LSEQ) {
#pragma unroll
            for (int gg = 0; gg < 4; gg++)
                xpn[gg] = __ldg(&xp[(size_t)(t + 1) * G4H + gg * 256 + rank * 32 + tid]);
        }

        // partial dot: this thread's 64-wide K slice of its gate row.
        // All lanes of a warp share kq -> identical SMEM addresses -> broadcast (conflict-free).
        float acc = 0.0f;
        const float4* h4 = (const float4*)&hb[p][k0];
#pragma unroll
        for (int q = 0; q < 16; q++) {
            float4 v = h4[q];
            acc += w[4 * q + 0] * v.x + w[4 * q + 1] * v.y
                 + w[4 * q + 2] * v.z + w[4 * q + 3] * v.w;
        }
        part[kq][lr] = acc;
        __syncthreads();

        if (tid < 32) {
            const int jj = tid;
            float gv[4];
#pragma unroll
            for (int gg = 0; gg < 4; gg++) {
                float s = part[0][gg * 32 + jj] + part[1][gg * 32 + jj]
                        + part[2][gg * 32 + jj] + part[3][gg * 32 + jj];
                gv[gg] = xpv[gg] + s;
            }
            float ii  = sigmoidf_(gv[0]);
            float ff  = sigmoidf_(gv[1]);
            float ggt = tanhf(gv[2]);
            float oo  = sigmoidf_(gv[3]);
            c = ff * c + ii * ggt;
            float hj = oo * tanhf(c);

            // broadcast h element to next-buffer of ALL cluster CTAs (incl. self)
            uint32_t laddr = s2u(&hb[p ^ 1][rank * 32 + jj]);
#pragma unroll
            for (int pc = 0; pc < 8; pc++)
                dsmem_st_f32(laddr, pc, hj);

            // emit to gmem in FINAL time order (backward direction un-reverses here)
            int tt = dir ? (LSEQ - 1 - t) : t;
            g_lstm_out[(size_t)tt * 512 + dir * 256 + rank * 32 + jj] = hj;

#pragma unroll
            for (int gg = 0; gg < 4; gg++) xpv[gg] = xpn[gg];
        }
        cluster_sync_();   // release DSMEM writes / retire all reads of hb[p]
        p ^= 1;
    }
}

// ---------------- kernel 3: feats = lstm_out @ W_out^T + b_out ----------------
// one warp per (t, tag)
__global__ __launch_bounds__(256, 4)
void feats_kernel(const float* __restrict__ Wout, const float* __restrict__ bout)
{
    int gw   = (blockIdx.x * blockDim.x + threadIdx.x) >> 5;
    int lane = threadIdx.x & 31;
    if (gw >= LSEQ * NT) return;
    int t = gw / NT, n = gw % NT;

    const float4* xr = (const float4*)(g_lstm_out + (size_t)t * 512);
    const float4* wr = (const float4*)(Wout + (size_t)n * 512);
    float acc = 0.0f;
#pragma unroll
    for (int q = 0; q < 4; q++) {
        float4 a = xr[q * 32 + lane];
        float4 b = __ldg(&wr[q * 32 + lane]);
        acc += a.x * b.x + a.y * b.y + a.z * b.z + a.w * b.w;
    }
#pragma unroll
    for (int off = 16; off; off >>= 1)
        acc += __shfl_down_sync(0xffffffffu, acc, off);
    if (lane == 0) g_feats[t * NT + n] = acc + bout[n];
}

// ---------------- kernel 4: Viterbi forward + backtrace ----------------
// Single block. Backpointers (4096x24 u8 = 96KB) stay in dynamic SMEM so the
// backtrace is an LDS pointer chase. feats staged in 256-step SMEM chunks.
#define BP_BYTES   (LSEQ * NT)               // 98304
#define FCH_BYTES  (256 * NT * 4)            // 24576
#define PATH_BYTES (LSEQ * 4)                // 16384
#define VSMEM      (BP_BYTES + FCH_BYTES + PATH_BYTES + 128)

__global__ void viterbi_kernel(const float* __restrict__ trans,
                               float* __restrict__ out, int out_size)
{
    extern __shared__ char sm[];
    unsigned char* bp  = (unsigned char*)sm;
    float*         fch = (float*)(sm + BP_BYTES);
    int*           path = (int*)(sm + BP_BYTES + FCH_BYTES);
    float*         fv  = (float*)(sm + BP_BYTES + FCH_BYTES + PATH_BYTES);
    __shared__ float score_s;

    const int tid = threadIdx.x;
    if (tid < NT) fv[tid] = (tid == START_TAG) ? 0.0f : NEGINF;

    float trow[NT];
    if (tid < NT) {
#pragma unroll
        for (int p_ = 0; p_ < NT; p_++) trow[p_] = trans[tid * NT + p_];
    }
    __syncthreads();

    for (int ch = 0; ch < LSEQ / 256; ch++) {
        const float* src = g_feats + (size_t)ch * 256 * NT;
        for (int i = tid; i < 256 * NT; i += blockDim.x) fch[i] = src[i];
        __syncthreads();

        if (tid < 32) {
            for (int s = 0; s < 256; s++) {
                int t = ch * 256 + s;
                float fvn = 0.0f;
                int bi = 0;
                if (tid < NT) {
                    float best = -3.4e38f;
#pragma unroll
                    for (int p_ = 0; p_ < NT; p_++) {
                        float sc = fv[p_] + trow[p_];
                        if (sc > best) { best = sc; bi = p_; }   // first-max (jnp.argmax)
                    }
                    fvn = best + fch[s * NT + tid];
                }
                __syncwarp();
                if (tid < NT) {
                    fv[tid] = fvn;
                    bp[t * NT + tid] = (unsigned char)bi;
                }
                __syncwarp();
            }
        }
        __syncthreads();
    }

    if (tid == 0) {
        float best = -3.4e38f; int bi = 0;
        for (int p_ = 0; p_ < NT; p_++) {
            float sc = fv[p_] + trans[STOP_TAG * NT + p_];
            if (sc > best) { best = sc; bi = p_; }
        }
        score_s = best;
        int tag = bi;
        for (int t = LSEQ - 1; t >= 0; t--) {
            path[t] = tag;
            tag = bp[t * NT + tag];
        }
    }
    __syncthreads();

    // output: tuple (path_score, best_path) flattened as float32
    if (out_size >= LSEQ + 1) {
        if (tid == 0) out[0] = score_s;
        for (int t = tid; t < LSEQ; t += blockDim.x) out[1 + t] = (float)path[t];
    } else if (out_size >= LSEQ) {
        for (int t = tid; t < LSEQ; t += blockDim.x) out[t] = (float)path[t];
    } else if (out_size >= 1) {
        if (tid == 0) out[0] = score_s;
    }
}

// ---------------- launch ----------------
extern "C" void kernel_launch(void* const* d_in, const int* in_sizes, int n_in,
                              void* d_out, int out_size)
{
    const int*   sent  = (const int*)d_in[0];
    const float* h0    = (const float*)d_in[1];
    const float* c0    = (const float*)d_in[2];
    const float* emb   = (const float*)d_in[3];
    const float* Wihf  = (const float*)d_in[4];
    const float* Whhf  = (const float*)d_in[5];
    const float* bihf  = (const float*)d_in[6];
    const float* bhhf  = (const float*)d_in[7];
    const float* Wihb  = (const float*)d_in[8];
    const float* Whhb  = (const float*)d_in[9];
    const float* bihb  = (const float*)d_in[10];
    const float* bhhb  = (const float*)d_in[11];
    const float* Wout  = (const float*)d_in[12];
    const float* bout  = (const float*)d_in[13];
    const float* trans = (const float*)d_in[14];

    cudaFuncSetAttribute(viterbi_kernel,
                         cudaFuncAttributeMaxDynamicSharedMemorySize, VSMEM);

    proj_kernel<<<dim3(LSEQ / 8, 2), 1024>>>(sent, emb, Wihf, bihf, bhhf,
                                             Wihb, bihb, bhhb);
    lstm_kernel<<<16, 512>>>(h0, c0, Whhf, Whhb);

    int nwarps  = LSEQ * NT;
    int nblocks = (nwarps * 32 + 255) / 256;
    feats_kernel<<<nblocks, 256>>>(Wout, bout);

    viterbi_kernel<<<1, 128, VSMEM>>>(trans, (float*)d_out, out_size);
}

// round 10
// speedup vs baseline: 1.4931x; 1.4931x over previous
#include <cuda_runtime.h>
#include <cuda_bf16.h>
#include <cstdint>
#include <math.h>

// Problem constants
#define LSEQ   4096
#define DEMB   256
#define HID    256          // per-direction hidden
#define G4H    1024         // 4*HID
#define NT     24
#define START_TAG 22
#define STOP_TAG  23
#define NEGINF (-1.0e6f)

// ---------------- scratch (device globals; no allocation allowed) ----------------
__device__ float g_xp[2][LSEQ * G4H];      // input projections per direction (scan order)
__device__ float g_lstm_out[LSEQ * 512];   // [t][0:256)=fwd h, [256:512)=bwd h (final order)
__device__ float g_feats[LSEQ * NT];

// ---------------- helpers ----------------
__device__ __forceinline__ uint32_t s2u(const void* p) {
    return (uint32_t)__cvta_generic_to_shared(p);
}
__device__ __forceinline__ void cluster_sync_() {
    asm volatile("barrier.cluster.arrive.aligned;" ::: "memory");
    asm volatile("barrier.cluster.wait.aligned;" ::: "memory");
}
__device__ __forceinline__ void mbar_init(uint32_t a, uint32_t cnt) {
    asm volatile("mbarrier.init.shared.b64 [%0], %1;" :: "r"(a), "r"(cnt) : "memory");
}
__device__ __forceinline__ void mbar_expect_tx(uint32_t a, uint32_t bytes) {
    asm volatile("mbarrier.arrive.expect_tx.shared.b64 _, [%0], %1;"
                 :: "r"(a), "r"(bytes) : "memory");
}
// proven form from ptx_helpers.cuh: acquire + bounded try_wait in a retry loop
__device__ __forceinline__ void mbar_wait(uint32_t a, uint32_t parity) {
    asm volatile(
        "{\n\t"
        ".reg .pred P1;\n"
        "LW_%=:\n\t"
        "mbarrier.try_wait.parity.acquire.cta.shared::cta.b64 P1, [%0], %1, 0x989680;\n\t"
        "@P1 bra LD_%=;\n\t"
        "bra LW_%=;\n"
        "LD_%=:\n\t"
        "}"
        :: "r"(a), "r"(parity) : "memory");
}
__device__ __forceinline__ uint32_t mapa_(uint32_t a, uint32_t pc) {
    uint32_t r;
    asm("mapa.shared::cluster.u32 %0, %1, %2;" : "=r"(r) : "r"(a), "r"(pc));
    return r;
}
__device__ __forceinline__ void st_async_tx(uint32_t raddr, float v, uint32_t rbar) {
    asm volatile("st.async.shared::cluster.mbarrier::complete_tx::bytes.b32 [%0], %1, [%2];"
                 :: "r"(raddr), "r"(__float_as_uint(v)), "r"(rbar) : "memory");
}
// fast, branch-free activations (__expf saturates cleanly at +-inf)
__device__ __forceinline__ float fsig(float x) {
    return __fdividef(1.0f, 1.0f + __expf(-x));
}
__device__ __forceinline__ float ftanh_(float x) {
    return 1.0f - __fdividef(2.0f, __expf(2.0f * x) + 1.0f);
}

// ---------------- kernel 1: embedding gather + input projection ----------------
__global__ __launch_bounds__(1024, 1)
void proj_kernel(const int* __restrict__ sent, const float* __restrict__ emb,
                 const float* __restrict__ Wf, const float* __restrict__ bihf,
                 const float* __restrict__ bhhf,
                 const float* __restrict__ Wb, const float* __restrict__ bihb,
                 const float* __restrict__ bhhb)
{
    __shared__ float4 xs[8][64];     // 8 timesteps x 256 floats
    const int dir = blockIdx.y;
    const int t0  = blockIdx.x * 8;
    const int tid = threadIdx.x;

    if (tid < 512) {
        int tt = tid >> 6, k4 = tid & 63;
        int s  = t0 + tt;
        int tok = sent[dir ? (LSEQ - 1 - s) : s];
        xs[tt][k4] = ((const float4*)emb)[(size_t)tok * 64 + k4];
    }
    __syncthreads();

    const float* W = dir ? Wb : Wf;
    const int row = tid;
    const float bias = dir ? (bihb[row] + bhhb[row]) : (bihf[row] + bhhf[row]);
    float acc[8];
#pragma unroll
    for (int i = 0; i < 8; i++) acc[i] = bias;

    const float4* W4 = (const float4*)(W + (size_t)row * DEMB);
#pragma unroll 8
    for (int k4 = 0; k4 < 64; k4++) {
        float4 w4 = __ldg(&W4[k4]);
#pragma unroll
        for (int tt = 0; tt < 8; tt++) {
            float4 x4 = xs[tt][k4];
            acc[tt] += w4.x * x4.x + w4.y * x4.y + w4.z * x4.z + w4.w * x4.w;
        }
    }
    float* out = g_xp[dir];
#pragma unroll
    for (int tt = 0; tt < 8; tt++)
        out[(size_t)(t0 + tt) * G4H + row] = acc[tt];
}

// ---------------- kernel 2: the sequential LSTM recurrence ----------------
// Grid: 16 CTAs, cluster of 8. Cluster 0 = forward, cluster 1 = backward.
// Each CTA owns h-slice [rank*32, rank*32+32); W_hh slice in registers as f32x2 pairs.
// h double-buffered in SMEM; remote fills via st.async + mbarrier complete_tx
// (1024 B per phase = 8 CTAs x 32 lanes x 4 B). No empty barriers: the
// full-barrier chain + double buffering provides backpressure.
//
// RE-ARM ORDERING (deadlock fix): full[p] is re-armed by tid0 IMMEDIATELY after
// its wait completes — i.e. before this CTA's __syncthreads, hence before any of
// this CTA's step-t st.async. A peer's step-(t+1) tx into our full[p] requires
// that peer to pass full[p^1] at t+1, which requires OUR step-t stores, which
// follow our __syncthreads, which tid0 only reaches after re-arming. So no tx
// can ever hit an un-armed barrier.
__global__ __launch_bounds__(512, 1) __cluster_dims__(8, 1, 1)
void lstm_kernel(const float* __restrict__ h0, const float* __restrict__ c0,
                 const float* __restrict__ Whh_f, const float* __restrict__ Whh_b)
{
    __shared__ __align__(16) float hb[2][HID];
    __shared__ float part[2][4][128];
    __shared__ __align__(8) unsigned long long mb_full[2];

    const int tid = threadIdx.x;
    uint32_t rank;
    asm("mov.u32 %0, %%cluster_ctarank;" : "=r"(rank));
    const int dir = blockIdx.x >> 3;

    const float* Whh = dir ? Whh_b : Whh_f;
    const float* xp  = g_xp[dir];

    const int lr = tid & 127;
    const int kq = tid >> 7;
    const int g  = lr >> 5;
    const int j  = lr & 31;
    const int grow = g * 256 + (int)rank * 32 + j;   // global gate row
    const int k0   = kq * 64;

    // W_hh slice as 32 packed f32x2 pairs (row is 1024B-aligned; k0*4 is 256B-aligned)
    unsigned long long w2[32];
    const unsigned long long* wrow =
        (const unsigned long long*)(Whh + (size_t)grow * HID + k0);
#pragma unroll
    for (int kk = 0; kk < 32; kk++) w2[kk] = __ldg(&wrow[kk]);

    const uint32_t fb0 = s2u(&mb_full[0]);
    const uint32_t fb1 = s2u(&mb_full[1]);

    // init + arm BEFORE cluster_sync so no tx can hit an un-armed barrier
    if (tid == 0) {
        mbar_init(fb0, 1);
        mbar_init(fb1, 1);
        mbar_expect_tx(fb0, 1024);   // phase 0: h0 fill
        mbar_expect_tx(fb1, 1024);   // phase 0: t=0 producer fill
    }
    __syncthreads();
    cluster_sync_();

    float c = 0.0f;
    float xpv[4] = {0.f, 0.f, 0.f, 0.f};
    if (tid < 32) {
        c = c0[dir * HID + rank * 32 + tid];
        float h0v = h0[dir * HID + rank * 32 + tid];
#pragma unroll
        for (int gg = 0; gg < 4; gg++)
            xpv[gg] = xp[gg * 256 + rank * 32 + tid];
        // broadcast h0 slice to hb[0] of all 8 CTAs (incl self), tx -> full[0]
        uint32_t lslot = s2u(&hb[0][rank * 32 + tid]);
#pragma unroll
        for (int pc = 0; pc < 8; pc++)
            st_async_tx(mapa_(lslot, pc), h0v, mapa_(fb0, pc));
    }

    uint32_t phF0 = 0, phF1 = 0;
    int p = 0;
    for (int t = 0; t < LSEQ; t++) {
        // wait h(t) in hb[p], then re-arm the SAME barrier for its next fill
        // (safe: see RE-ARM ORDERING note above)
        if (p == 0) {
            mbar_wait(fb0, phF0); phF0 ^= 1;
            if (tid == 0) mbar_expect_tx(fb0, 1024);
        } else {
            mbar_wait(fb1, phF1); phF1 ^= 1;
            if (tid == 0) mbar_expect_tx(fb1, 1024);
        }

        // prefetch next step's xp rows (hidden behind this step's dot compute)
        float xpn[4] = {0.f, 0.f, 0.f, 0.f};
        if (tid < 32 && t + 1 < LSEQ) {
#pragma unroll
            for (int gg = 0; gg < 4; gg++)
                xpn[gg] = __ldg(&xp[(size_t)(t + 1) * G4H + gg * 256 + rank * 32 + tid]);
        }

        // partial dot via packed f32x2 FMA (broadcast LDS.128, conflict-free)
        const ulonglong2* h8 = (const ulonglong2*)&hb[p][k0];
        unsigned long long a0 = 0ull, a1 = 0ull;
#pragma unroll
        for (int q = 0; q < 16; q++) {
            ulonglong2 hv = h8[q];
            asm("fma.rn.f32x2 %0, %1, %2, %0;" : "+l"(a0) : "l"(w2[2 * q]),     "l"(hv.x));
            asm("fma.rn.f32x2 %0, %1, %2, %0;" : "+l"(a1) : "l"(w2[2 * q + 1]), "l"(hv.y));
        }
        asm("add.rn.f32x2 %0, %1, %2;" : "=l"(a0) : "l"(a0), "l"(a1));
        uint32_t alo, ahi;
        asm("mov.b64 {%0,%1}, %2;" : "=r"(alo), "=r"(ahi) : "l"(a0));
        part[p][kq][lr] = __uint_as_float(alo) + __uint_as_float(ahi);
        __syncthreads();      // part[p] ready; all local reads of hb[p] retired

        if (tid < 32) {
            const int jj = tid;
            float gv[4];
#pragma unroll
            for (int gg = 0; gg < 4; gg++) {
                float s = part[p][0][gg * 32 + jj] + part[p][1][gg * 32 + jj]
                        + part[p][2][gg * 32 + jj] + part[p][3][gg * 32 + jj];
                gv[gg] = xpv[gg] + s;
            }
            float ii  = fsig(gv[0]);
            float ff  = fsig(gv[1]);
            float ggt = ftanh_(gv[2]);
            float oo  = fsig(gv[3]);
            c = ff * c + ii * ggt;
            float hj = oo * ftanh_(c);

            // emit to gmem in FINAL time order (backward direction un-reverses here)
            int tt = dir ? (LSEQ - 1 - t) : t;
            g_lstm_out[(size_t)tt * 512 + dir * 256 + rank * 32 + jj] = hj;

            if (t + 1 < LSEQ) {
                uint32_t lslot = s2u(&hb[p ^ 1][rank * 32 + jj]);
                uint32_t fbn   = (p == 0) ? fb1 : fb0;
#pragma unroll
                for (int pc = 0; pc < 8; pc++)
                    st_async_tx(mapa_(lslot, pc), hj, mapa_(fbn, pc));
            }
#pragma unroll
            for (int gg = 0; gg < 4; gg++) xpv[gg] = xpn[gg];
        }
        // no second __syncthreads: part is double-buffered by p; reuse of part[p]
        // at t+2 is ordered through two full-barrier generations (each CTA's
        // t+2 fill requires our step-(t+1) stores, which follow our step-(t+1)
        // __syncthreads, which follows this CTA's step-t part[p] reads... and
        // symmetric for every peer, since every peer's stores gate every wait).
        p ^= 1;
    }
}

// ---------------- kernel 3: feats = lstm_out @ W_out^T + b_out ----------------
// one warp per (t, tag)
__global__ __launch_bounds__(256, 4)
void feats_kernel(const float* __restrict__ Wout, const float* __restrict__ bout)
{
    int gw   = (blockIdx.x * blockDim.x + threadIdx.x) >> 5;
    int lane = threadIdx.x & 31;
    if (gw >= LSEQ * NT) return;
    int t = gw / NT, n = gw % NT;

    const float4* xr = (const float4*)(g_lstm_out + (size_t)t * 512);
    const float4* wr = (const float4*)(Wout + (size_t)n * 512);
    float acc = 0.0f;
#pragma unroll
    for (int q = 0; q < 4; q++) {
        float4 a = xr[q * 32 + lane];
        float4 b = __ldg(&wr[q * 32 + lane]);
        acc += a.x * b.x + a.y * b.y + a.z * b.z + a.w * b.w;
    }
#pragma unroll
    for (int off = 16; off; off >>= 1)
        acc += __shfl_down_sync(0xffffffffu, acc, off);
    if (lane == 0) g_feats[t * NT + n] = acc + bout[n];
}

// ---------------- kernel 4: Viterbi forward + backtrace ----------------
// fv lives in registers (one tag per lane), broadcast via shfl (no syncwarp),
// first-index argmax via contiguous-pair FSEL tree. bp in SMEM for LDS backtrace.
#define BP_BYTES   (LSEQ * NT)               // 98304
#define FCH_BYTES  (256 * NT * 4)            // 24576
#define PATH_BYTES (LSEQ * 4)                // 16384
#define VSMEM      (BP_BYTES + FCH_BYTES + PATH_BYTES + 128)

// combine keeping 'a' (lower index range) on ties -> jnp.argmax first-max
__device__ __forceinline__ void amax2_(float& v, int& i, float v2, int i2) {
    bool ge = (v >= v2);
    v = ge ? v : v2;
    i = ge ? i : i2;
}

__global__ void viterbi_kernel(const float* __restrict__ trans,
                               float* __restrict__ out, int out_size)
{
    extern __shared__ char sm[];
    unsigned char* bp   = (unsigned char*)sm;
    float*         fch  = (float*)(sm + BP_BYTES);
    int*           path = (int*)(sm + BP_BYTES + FCH_BYTES);
    __shared__ float score_s;

    const int tid = threadIdx.x;

    float fvr = (tid == START_TAG) ? 0.0f : NEGINF;
    float trow[NT];
    if (tid < NT) {
#pragma unroll
        for (int p_ = 0; p_ < NT; p_++) trow[p_] = trans[tid * NT + p_];
    } else {
#pragma unroll
        for (int p_ = 0; p_ < NT; p_++) trow[p_] = 0.0f;
    }
    __syncthreads();

    for (int ch = 0; ch < LSEQ / 256; ch++) {
        const float* src = g_feats + (size_t)ch * 256 * NT;
        for (int i = tid; i < 256 * NT; i += blockDim.x) fch[i] = src[i];
        __syncthreads();

        if (tid < 32) {
            for (int s = 0; s < 256; s++) {
                int t = ch * 256 + s;
                float sc[32];
#pragma unroll
                for (int k = 0; k < NT; k++)
                    sc[k] = __shfl_sync(0xffffffffu, fvr, k) + trow[k];
#pragma unroll
                for (int k = NT; k < 32; k++) sc[k] = -3.4e38f;

                // first-max tree: at every level the a-side covers strictly
                // smaller original indices, so leftmost tie-break is preserved
                float v[16]; int ix[16];
#pragma unroll
                for (int m = 0; m < 16; m++) {
                    bool ge = (sc[2 * m] >= sc[2 * m + 1]);
                    v[m]  = ge ? sc[2 * m] : sc[2 * m + 1];
                    ix[m] = ge ? (2 * m) : (2 * m + 1);
                }
#pragma unroll
                for (int m = 0; m < 8; m++) amax2_(v[m], ix[m], v[m + 8], ix[m + 8]);
#pragma unroll
                for (int m = 0; m < 4; m++) amax2_(v[m], ix[m], v[m + 4], ix[m + 4]);
#pragma unroll
                for (int m = 0; m < 2; m++) amax2_(v[m], ix[m], v[m + 2], ix[m + 2]);
                amax2_(v[0], ix[0], v[1], ix[1]);

                float fval = (tid < NT) ? fch[s * NT + tid] : 0.0f;
                fvr = v[0] + fval;
                if (tid < NT) bp[t * NT + tid] = (unsigned char)ix[0];
            }
        }
        __syncthreads();
    }

    if (tid < 32) {
        // terminal: fv + trans[STOP]
        float sc[32];
#pragma unroll
        for (int k = 0; k < NT; k++)
            sc[k] = __shfl_sync(0xffffffffu, fvr, k) + __ldg(&trans[STOP_TAG * NT + k]);
#pragma unroll
        for (int k = NT; k < 32; k++) sc[k] = -3.4e38f;
        float v[16]; int ix[16];
#pragma unroll
        for (int m = 0; m < 16; m++) {
            bool ge = (sc[2 * m] >= sc[2 * m + 1]);
            v[m]  = ge ? sc[2 * m] : sc[2 * m + 1];
            ix[m] = ge ? (2 * m) : (2 * m + 1);
        }
#pragma unroll
        for (int m = 0; m < 8; m++) amax2_(v[m], ix[m], v[m + 8], ix[m + 8]);
#pragma unroll
        for (int m = 0; m < 4; m++) amax2_(v[m], ix[m], v[m + 4], ix[m + 4]);
#pragma unroll
        for (int m = 0; m < 2; m++) amax2_(v[m], ix[m], v[m + 2], ix[m + 2]);
        amax2_(v[0], ix[0], v[1], ix[1]);

        if (tid == 0) {
            score_s = v[0];
            int tag = ix[0];
            for (int t = LSEQ - 1; t >= 0; t--) {
                path[t] = tag;
                tag = bp[t * NT + tag];
            }
        }
    }
    __syncthreads();

    // output: tuple (path_score, best_path) flattened as float32
    if (out_size >= LSEQ + 1) {
        if (tid == 0) out[0] = score_s;
        for (int t = tid; t < LSEQ; t += blockDim.x) out[1 + t] = (float)path[t];
    } else if (out_size >= LSEQ) {
        for (int t = tid; t < LSEQ; t += blockDim.x) out[t] = (float)path[t];
    } else if (out_size >= 1) {
        if (tid == 0) out[0] = score_s;
    }
}

// ---------------- launch ----------------
extern "C" void kernel_launch(void* const* d_in, const int* in_sizes, int n_in,
                              void* d_out, int out_size)
{
    const int*   sent  = (const int*)d_in[0];
    const float* h0    = (const float*)d_in[1];
    const float* c0    = (const float*)d_in[2];
    const float* emb   = (const float*)d_in[3];
    const float* Wihf  = (const float*)d_in[4];
    const float* Whhf  = (const float*)d_in[5];
    const float* bihf  = (const float*)d_in[6];
    const float* bhhf  = (const float*)d_in[7];
    const float* Wihb  = (const float*)d_in[8];
    const float* Whhb  = (const float*)d_in[9];
    const float* bihb  = (const float*)d_in[10];
    const float* bhhb  = (const float*)d_in[11];
    const float* Wout  = (const float*)d_in[12];
    const float* bout  = (const float*)d_in[13];
    const float* trans = (const float*)d_in[14];

    cudaFuncSetAttribute(viterbi_kernel,
                         cudaFuncAttributeMaxDynamicSharedMemorySize, VSMEM);

    proj_kernel<<<dim3(LSEQ / 8, 2), 1024>>>(sent, emb, Wihf, bihf, bhhf,
                                             Wihb, bihb, bhhb);
    lstm_kernel<<<16, 512>>>(h0, c0, Whhf, Whhb);

    int nwarps  = LSEQ * NT;
    int nblocks = (nwarps * 32 + 255) / 256;
    feats_kernel<<<nblocks, 256>>>(Wout, bout);

    viterbi_kernel<<<1, 128, VSMEM>>>(trans, (float*)d_out, out_size);
}